// round 1
// baseline (speedup 1.0000x reference)
#include <cuda_runtime.h>
#include <cstdint>

#define NN 40000
#define EE 640000
#define RRL 8
#define HH 128
#define CC 64
#define NRSEG (NN*RRL)

// ---------------- scratch (__device__ globals; no allocation) ----------------
__device__ int   g_cntd[NN];        // edges per dst
__device__ int   g_cnt2[NRSEG];     // edges per (dst,rel)
__device__ float g_inv[NRSEG];      // 1/max(cnt2,1)
__device__ int   g_offs[NN];        // CSR start per dst
__device__ int   g_cursor[NN];
__device__ int   g_sorted[EE];      // (rel<<16)|src, grouped by dst
__device__ int   g_bsum[40];
__device__ float g_h[(size_t)NN*HH];          // layer-1 output, 20.5 MB
__device__ float g_hall[(size_t)RRL*NN*CC];   // h @ W2[r], 81.9 MB

typedef unsigned long long ull;

__device__ __forceinline__ ull pack2(float a, float b) {
    ull r; asm("mov.b64 %0, {%1,%2};" : "=l"(r) : "f"(a), "f"(b)); return r;
}
__device__ __forceinline__ ull fma2(ull a, ull b, ull c) {
    ull d; asm("fma.rn.f32x2 %0, %1, %2, %3;" : "=l"(d) : "l"(a), "l"(b), "l"(c)); return d;
}
__device__ __forceinline__ float2 unpack2(ull v) {
    float2 r; asm("mov.b64 {%0,%1}, %2;" : "=f"(r.x), "=f"(r.y) : "l"(v)); return r;
}

// ---------------- CSR build ----------------
__global__ void k_zero() {
    int i = blockIdx.x * blockDim.x + threadIdx.x;
    int stride = gridDim.x * blockDim.x;
    for (; i < NRSEG; i += stride) {
        g_cnt2[i] = 0;
        if (i < NN) { g_cntd[i] = 0; g_cursor[i] = 0; }
    }
}

__global__ void k_hist(const int* __restrict__ ei, const int* __restrict__ et) {
    int e = blockIdx.x * blockDim.x + threadIdx.x;
    if (e >= EE) return;
    int dst = ei[EE + e];
    int rel = et[e];
    atomicAdd(&g_cntd[dst], 1);
    atomicAdd(&g_cnt2[dst * RRL + rel], 1);
}

__global__ void k_inv() {
    int i = blockIdx.x * blockDim.x + threadIdx.x;
    if (i < NRSEG) {
        int c = g_cnt2[i];
        g_inv[i] = 1.0f / (float)(c > 0 ? c : 1);
    }
}

__global__ void k_scan1() {
    __shared__ int s[1024];
    int tid = threadIdx.x;
    int i = blockIdx.x * 1024 + tid;
    int v = (i < NN) ? g_cntd[i] : 0;
    s[tid] = v;
    __syncthreads();
    for (int off = 1; off < 1024; off <<= 1) {
        int t = (tid >= off) ? s[tid - off] : 0;
        __syncthreads();
        s[tid] += t;
        __syncthreads();
    }
    if (i < NN) g_offs[i] = s[tid] - v;
    if (tid == 1023) g_bsum[blockIdx.x] = s[1023];
}

__global__ void k_scan2() {
    int run = 0;
    for (int j = 0; j < 40; j++) { int t = g_bsum[j]; g_bsum[j] = run; run += t; }
}

__global__ void k_scan3() {
    int i = blockIdx.x * blockDim.x + threadIdx.x;
    if (i < NN) g_offs[i] += g_bsum[i >> 10];
}

__global__ void k_perm(const int* __restrict__ ei, const int* __restrict__ et) {
    int e = blockIdx.x * blockDim.x + threadIdx.x;
    if (e >= EE) return;
    int dst = ei[EE + e];
    int rel = et[e];
    int src = ei[e];
    int pos = g_offs[dst] + atomicAdd(&g_cursor[dst], 1);
    g_sorted[pos] = (rel << 16) | src;
}

// ---------------- layer 1: warp per dst, no atomics ----------------
__global__ void k_layer1(const float* __restrict__ W1, const float* __restrict__ root1,
                         const float* __restrict__ b1) {
    int w = (blockIdx.x * blockDim.x + threadIdx.x) >> 5;
    int lane = threadIdx.x & 31;
    if (w >= NN) return;
    int beg = g_offs[w];
    int cnt = g_cntd[w];
    float4 acc = ((const float4*)root1)[w * 32 + lane];
    float4 bb = ((const float4*)b1)[lane];
    acc.x += bb.x; acc.y += bb.y; acc.z += bb.z; acc.w += bb.w;
    const float4* W1v = (const float4*)W1;
    int invbase = w * RRL;
    int i = 0;
    for (; i + 4 <= cnt; i += 4) {
        int p0 = g_sorted[beg + i + 0];
        int p1 = g_sorted[beg + i + 1];
        int p2 = g_sorted[beg + i + 2];
        int p3 = g_sorted[beg + i + 3];
        float s0 = g_inv[invbase + (p0 >> 16)];
        float s1 = g_inv[invbase + (p1 >> 16)];
        float s2 = g_inv[invbase + (p2 >> 16)];
        float s3 = g_inv[invbase + (p3 >> 16)];
        float4 v0 = W1v[(size_t)((p0 >> 16) * NN + (p0 & 0xFFFF)) * 32 + lane];
        float4 v1 = W1v[(size_t)((p1 >> 16) * NN + (p1 & 0xFFFF)) * 32 + lane];
        float4 v2 = W1v[(size_t)((p2 >> 16) * NN + (p2 & 0xFFFF)) * 32 + lane];
        float4 v3 = W1v[(size_t)((p3 >> 16) * NN + (p3 & 0xFFFF)) * 32 + lane];
        acc.x += v0.x*s0 + v1.x*s1 + v2.x*s2 + v3.x*s3;
        acc.y += v0.y*s0 + v1.y*s1 + v2.y*s2 + v3.y*s3;
        acc.z += v0.z*s0 + v1.z*s1 + v2.z*s2 + v3.z*s3;
        acc.w += v0.w*s0 + v1.w*s1 + v2.w*s2 + v3.w*s3;
    }
    for (; i < cnt; i++) {
        int p = g_sorted[beg + i];
        float s = g_inv[invbase + (p >> 16)];
        float4 v = W1v[(size_t)((p >> 16) * NN + (p & 0xFFFF)) * 32 + lane];
        acc.x += v.x * s; acc.y += v.y * s; acc.z += v.z * s; acc.w += v.w * s;
    }
    acc.x = fmaxf(acc.x, 0.0f);
    acc.y = fmaxf(acc.y, 0.0f);
    acc.z = fmaxf(acc.z, 0.0f);
    acc.w = fmaxf(acc.w, 0.0f);
    ((float4*)g_h)[w * 32 + lane] = acc;
}

// ---------------- GEMM: h_all[r] = h @ W2[r]; r==8 -> out = h @ root2 + b2 ----------------
#define HS 132
#define GEMM_SMEM ((64*HS + 128*64) * 4)

__global__ void k_gemm(const float* __restrict__ W2, const float* __restrict__ root2,
                       const float* __restrict__ b2, float* __restrict__ out) {
    extern __shared__ float sm[];
    float* h_s = sm;             // [64][HS]
    float* w_s = sm + 64 * HS;   // [128][64]
    int t = threadIdx.x;         // 256 threads
    int n0 = blockIdx.x * 64;

    // load h tile [64 rows][128 k], padded stride HS for conflict-free column reads
#pragma unroll
    for (int j = 0; j < 8; j++) {
        int f = t + j * 256;         // float4 id 0..2047
        int row = f >> 5;
        int kq = f & 31;
        float4 v = ((const float4*)g_h)[((size_t)(n0 + row)) * 32 + kq];
        *(float4*)&h_s[row * HS + (kq << 2)] = v;
    }

    int tc = t & 7, tr = t >> 3;
    int c0 = tc << 3;    // 8 cols per thread
    int nr0 = tr << 1;   // 2 rows per thread
    int rbase = blockIdx.y * 3;

    for (int rr = 0; rr < 3; rr++) {
        int r = rbase + rr;
        const float4* wsrc = (const float4*)((r < 8) ? (W2 + (size_t)r * HH * CC) : root2);
        __syncthreads();   // protects w_s reuse AND first-iter h_s visibility
#pragma unroll
        for (int j = 0; j < 8; j++) {
            int f = t + j * 256;
            ((float4*)w_s)[f] = wsrc[f];
        }
        __syncthreads();

        ull a00=0,a01=0,a02=0,a03=0,a10=0,a11=0,a12=0,a13=0;
#pragma unroll 8
        for (int k = 0; k < 128; k++) {
            float x0 = h_s[nr0 * HS + k];
            float x1 = h_s[(nr0 + 1) * HS + k];
            ull pa0 = pack2(x0, x0);
            ull pa1 = pack2(x1, x1);
            ulonglong2 b0 = *(const ulonglong2*)&w_s[k * 64 + c0];
            ulonglong2 b1 = *(const ulonglong2*)&w_s[k * 64 + c0 + 4];
            a00 = fma2(pa0, b0.x, a00); a01 = fma2(pa0, b0.y, a01);
            a02 = fma2(pa0, b1.x, a02); a03 = fma2(pa0, b1.y, a03);
            a10 = fma2(pa1, b0.x, a10); a11 = fma2(pa1, b0.y, a11);
            a12 = fma2(pa1, b1.x, a12); a13 = fma2(pa1, b1.y, a13);
        }

        float2 o00=unpack2(a00), o01=unpack2(a01), o02=unpack2(a02), o03=unpack2(a03);
        float2 o10=unpack2(a10), o11=unpack2(a11), o12=unpack2(a12), o13=unpack2(a13);
        int n = n0 + nr0;
        if (n < NN) {
            if (r < 8) {
                float* d0 = &g_hall[((size_t)r * NN + n) * CC + c0];
                ((float4*)d0)[0] = make_float4(o00.x, o00.y, o01.x, o01.y);
                ((float4*)d0)[1] = make_float4(o02.x, o02.y, o03.x, o03.y);
                float* d1 = d0 + CC;
                ((float4*)d1)[0] = make_float4(o10.x, o10.y, o11.x, o11.y);
                ((float4*)d1)[1] = make_float4(o12.x, o12.y, o13.x, o13.y);
            } else {
                float4 bb0 = ((const float4*)b2)[c0 >> 2];
                float4 bb1 = ((const float4*)b2)[(c0 >> 2) + 1];
                float* d0 = &out[(size_t)n * CC + c0];
                ((float4*)d0)[0] = make_float4(o00.x+bb0.x, o00.y+bb0.y, o01.x+bb0.z, o01.y+bb0.w);
                ((float4*)d0)[1] = make_float4(o02.x+bb1.x, o02.y+bb1.y, o03.x+bb1.z, o03.y+bb1.w);
                float* d1 = d0 + CC;
                ((float4*)d1)[0] = make_float4(o10.x+bb0.x, o10.y+bb0.y, o11.x+bb0.z, o11.y+bb0.w);
                ((float4*)d1)[1] = make_float4(o12.x+bb1.x, o12.y+bb1.y, o13.x+bb1.z, o13.y+bb1.w);
            }
        }
    }
}

// ---------------- layer 2: warp per dst, gather h_all, accumulate into out ----------------
__global__ void k_layer2(float* __restrict__ out) {
    int w = (blockIdx.x * blockDim.x + threadIdx.x) >> 5;
    int lane = threadIdx.x & 31;
    if (w >= NN) return;
    int beg = g_offs[w];
    int cnt = g_cntd[w];
    float2 acc = ((float2*)out)[w * 32 + lane];   // h@root2 + b2 from k_gemm
    const float2* hv = (const float2*)g_hall;
    int invbase = w * RRL;
    int i = 0;
    for (; i + 4 <= cnt; i += 4) {
        int p0 = g_sorted[beg + i + 0];
        int p1 = g_sorted[beg + i + 1];
        int p2 = g_sorted[beg + i + 2];
        int p3 = g_sorted[beg + i + 3];
        float s0 = g_inv[invbase + (p0 >> 16)];
        float s1 = g_inv[invbase + (p1 >> 16)];
        float s2 = g_inv[invbase + (p2 >> 16)];
        float s3 = g_inv[invbase + (p3 >> 16)];
        float2 v0 = hv[(size_t)((p0 >> 16) * NN + (p0 & 0xFFFF)) * 32 + lane];
        float2 v1 = hv[(size_t)((p1 >> 16) * NN + (p1 & 0xFFFF)) * 32 + lane];
        float2 v2 = hv[(size_t)((p2 >> 16) * NN + (p2 & 0xFFFF)) * 32 + lane];
        float2 v3 = hv[(size_t)((p3 >> 16) * NN + (p3 & 0xFFFF)) * 32 + lane];
        acc.x += v0.x*s0 + v1.x*s1 + v2.x*s2 + v3.x*s3;
        acc.y += v0.y*s0 + v1.y*s1 + v2.y*s2 + v3.y*s3;
    }
    for (; i < cnt; i++) {
        int p = g_sorted[beg + i];
        float s = g_inv[invbase + (p >> 16)];
        float2 v = hv[(size_t)((p >> 16) * NN + (p & 0xFFFF)) * 32 + lane];
        acc.x += v.x * s; acc.y += v.y * s;
    }
    ((float2*)out)[w * 32 + lane] = acc;
}

// ---------------- launch ----------------
extern "C" void kernel_launch(void* const* d_in, const int* in_sizes, int n_in,
                              void* d_out, int out_size) {
    (void)in_sizes; (void)n_in; (void)out_size;
    const int*   ei    = (const int*)d_in[0];
    const int*   et    = (const int*)d_in[1];
    const float* W1    = (const float*)d_in[2];
    const float* root1 = (const float*)d_in[3];
    const float* b1    = (const float*)d_in[4];
    const float* W2    = (const float*)d_in[5];
    const float* root2 = (const float*)d_in[6];
    const float* b2    = (const float*)d_in[7];
    float* out = (float*)d_out;

    k_zero<<<592, 256>>>();
    k_hist<<<(EE + 255) / 256, 256>>>(ei, et);
    k_inv<<<(NRSEG + 255) / 256, 256>>>();
    k_scan1<<<40, 1024>>>();
    k_scan2<<<1, 1>>>();
    k_scan3<<<(NN + 255) / 256, 256>>>();
    k_perm<<<(EE + 255) / 256, 256>>>(ei, et);
    k_layer1<<<NN / 8, 256>>>(W1, root1, b1);
    cudaFuncSetAttribute(k_gemm, cudaFuncAttributeMaxDynamicSharedMemorySize, GEMM_SMEM);
    k_gemm<<<dim3(625, 3), 256, GEMM_SMEM>>>(W2, root2, b2, out);
    k_layer2<<<NN / 8, 256>>>(out);
}

// round 3
// speedup vs baseline: 2.1008x; 2.1008x over previous
#include <cuda_runtime.h>
#include <cstdint>

#define NN 40000
#define EE 640000
#define RRL 8
#define HH 128
#define CC 64
#define NRSEG (NN*RRL)
#define NTILES 313          // ceil(40000/128)

// ---------------- scratch (__device__ globals; no allocation) ----------------
__device__ int   g_cntd[NN];
__device__ int   g_cnt2[NRSEG];
__device__ float g_inv[NRSEG];
__device__ int   g_offs[NN];
__device__ int   g_cursor[NN];
__device__ int   g_sorted[EE];          // (rel<<16)|src, grouped by dst
__device__ int   g_bsum[40];
__device__ int   g_bflag[40];
__device__ float g_h[(size_t)NTILES * 128 * HH];   // layer-1 out (rows >=NN read-only garbage)
__device__ uint32_t g_w2t[9 * CC * HH];            // W2^T / root2^T as tf32 bits [m][c][k]
__device__ float g_hall[(size_t)RRL * NN * CC];    // h @ W2[r], 81.9 MB

__device__ __forceinline__ uint32_t f2tf(float x) {
    uint32_t r; asm("cvt.rna.tf32.f32 %0, %1;" : "=r"(r) : "f"(x)); return r;
}

// ---------------- fused: zero counters + transpose W2/root2 to tf32 [m][c][k] ----------------
__global__ void k_fused0(const float* __restrict__ W2, const float* __restrict__ root2) {
    int i = blockIdx.x * blockDim.x + threadIdx.x;
    int stride = gridDim.x * blockDim.x;
    for (int j = i; j < NRSEG; j += stride) {
        g_cnt2[j] = 0;
        if (j < NN) { g_cntd[j] = 0; g_cursor[j] = 0; }
        if (j < 40) { g_bflag[j] = 0; }
    }
    for (int j = i; j < 9 * CC * HH; j += stride) {
        int m = j >> 13;
        int rem = j & 8191;
        int c = rem >> 7;
        int k = rem & 127;
        float v = (m < 8) ? W2[((size_t)m * HH + k) * CC + c] : root2[(size_t)k * CC + c];
        g_w2t[j] = f2tf(v);
    }
}

__global__ void k_hist(const int* __restrict__ ei, const int* __restrict__ et) {
    int e = blockIdx.x * blockDim.x + threadIdx.x;
    if (e >= EE) return;
    int dst = ei[EE + e];
    int rel = et[e];
    atomicAdd(&g_cntd[dst], 1);
    atomicAdd(&g_cnt2[dst * RRL + rel], 1);
}

// ---------------- single-kernel scan (decoupled lookback) + inv ----------------
__global__ void k_scan() {
    __shared__ int s[1024];
    __shared__ int sprev;
    int b = blockIdx.x, tid = threadIdx.x;
    int i = b * 1024 + tid;
    int v = (i < NN) ? g_cntd[i] : 0;
    s[tid] = v;
    __syncthreads();
    for (int off = 1; off < 1024; off <<= 1) {
        int t = (tid >= off) ? s[tid - off] : 0;
        __syncthreads();
        s[tid] += t;
        __syncthreads();
    }
    if (tid == 1023) {
        int total = s[1023];
        int prev = 0;
        if (b > 0) {
            while (atomicAdd(&g_bflag[b - 1], 0) == 0) { }
            prev = g_bsum[b - 1];
        }
        g_bsum[b] = prev + total;
        __threadfence();
        atomicExch(&g_bflag[b], 1);
        sprev = prev;
    }
    // overlap: inv over (dst,rel) counts
    for (int j = b * 1024 + tid; j < NRSEG; j += 40 * 1024) {
        int c = g_cnt2[j];
        g_inv[j] = 1.0f / (float)(c > 0 ? c : 1);
    }
    __syncthreads();
    if (i < NN) g_offs[i] = s[tid] - v + sprev;
}

__global__ void k_perm(const int* __restrict__ ei, const int* __restrict__ et) {
    int e = blockIdx.x * blockDim.x + threadIdx.x;
    if (e >= EE) return;
    int dst = ei[EE + e];
    int rel = et[e];
    int src = ei[e];
    int pos = g_offs[dst] + atomicAdd(&g_cursor[dst], 1);
    g_sorted[pos] = (rel << 16) | src;
}

// ---------------- layer 1: warp per dst, no atomics ----------------
__global__ void k_layer1(const float* __restrict__ W1, const float* __restrict__ root1,
                         const float* __restrict__ b1) {
    int w = (blockIdx.x * blockDim.x + threadIdx.x) >> 5;
    int lane = threadIdx.x & 31;
    if (w >= NN) return;
    int beg = g_offs[w];
    int cnt = g_cntd[w];
    float4 acc = ((const float4*)root1)[w * 32 + lane];
    float4 bb = ((const float4*)b1)[lane];
    acc.x += bb.x; acc.y += bb.y; acc.z += bb.z; acc.w += bb.w;
    const float4* W1v = (const float4*)W1;
    int invbase = w * RRL;
    int i = 0;
    for (; i + 4 <= cnt; i += 4) {
        int p0 = g_sorted[beg + i + 0];
        int p1 = g_sorted[beg + i + 1];
        int p2 = g_sorted[beg + i + 2];
        int p3 = g_sorted[beg + i + 3];
        float s0 = g_inv[invbase + (p0 >> 16)];
        float s1 = g_inv[invbase + (p1 >> 16)];
        float s2 = g_inv[invbase + (p2 >> 16)];
        float s3 = g_inv[invbase + (p3 >> 16)];
        float4 v0 = W1v[(size_t)((p0 >> 16) * NN + (p0 & 0xFFFF)) * 32 + lane];
        float4 v1 = W1v[(size_t)((p1 >> 16) * NN + (p1 & 0xFFFF)) * 32 + lane];
        float4 v2 = W1v[(size_t)((p2 >> 16) * NN + (p2 & 0xFFFF)) * 32 + lane];
        float4 v3 = W1v[(size_t)((p3 >> 16) * NN + (p3 & 0xFFFF)) * 32 + lane];
        acc.x += v0.x*s0 + v1.x*s1 + v2.x*s2 + v3.x*s3;
        acc.y += v0.y*s0 + v1.y*s1 + v2.y*s2 + v3.y*s3;
        acc.z += v0.z*s0 + v1.z*s1 + v2.z*s2 + v3.z*s3;
        acc.w += v0.w*s0 + v1.w*s1 + v2.w*s2 + v3.w*s3;
    }
    for (; i < cnt; i++) {
        int p = g_sorted[beg + i];
        float s = g_inv[invbase + (p >> 16)];
        float4 v = W1v[(size_t)((p >> 16) * NN + (p & 0xFFFF)) * 32 + lane];
        acc.x += v.x * s; acc.y += v.y * s; acc.z += v.z * s; acc.w += v.w * s;
    }
    acc.x = fmaxf(acc.x, 0.0f);
    acc.y = fmaxf(acc.y, 0.0f);
    acc.z = fmaxf(acc.z, 0.0f);
    acc.w = fmaxf(acc.w, 0.0f);
    ((float4*)g_h)[w * 32 + lane] = acc;
}

// ---------------- GEMM via tf32 mma.sync: h_all[r] = h @ W2[r]; r==8 -> out ----------------
#define PAD 132
#define SM_TOTAL ((128 + 64) * PAD * 4)   // 101376 bytes

__global__ void __launch_bounds__(256, 2) k_gemm(const float* __restrict__ b2,
                                                 float* __restrict__ out) {
    extern __shared__ uint32_t sm32[];
    uint32_t* As = sm32;               // [128][PAD] tf32 bits
    uint32_t* Bs = sm32 + 128 * PAD;   // [64][PAD]  tf32 bits (B^T: [c][k])
    int t = threadIdx.x;
    int tile = blockIdx.x;
    int r = blockIdx.y;

    // stage A (rows = nodes, cols = k), convert to tf32
    const float4* asrc = (const float4*)(g_h + (size_t)tile * 128 * HH);
#pragma unroll
    for (int j = 0; j < 16; j++) {
        int f = t + j * 256;           // 0..4095 float4s
        int row = f >> 5, q = f & 31;
        float4 v = asrc[f];
        uint32_t* d = &As[row * PAD + (q << 2)];
        d[0] = f2tf(v.x); d[1] = f2tf(v.y); d[2] = f2tf(v.z); d[3] = f2tf(v.w);
    }
    // stage B (already tf32 bits): [c][k]
    const uint4* bsrc = (const uint4*)(g_w2t + (size_t)r * CC * HH);
#pragma unroll
    for (int j = 0; j < 8; j++) {
        int f = t + j * 256;           // 0..2047 uint4s
        int row = f >> 5, q = f & 31;
        *(uint4*)&Bs[row * PAD + (q << 2)] = bsrc[f];
    }
    __syncthreads();

    int warp = t >> 5, lane = t & 31;
    int g = lane >> 2;        // groupID 0..7
    int kq = lane & 3;        // threadID_in_group
    int rA = warp * 16 + g;   // A row for a0/a2

    float acc[8][4];
#pragma unroll
    for (int nt = 0; nt < 8; nt++)
#pragma unroll
        for (int q = 0; q < 4; q++) acc[nt][q] = 0.0f;

#pragma unroll
    for (int ks = 0; ks < 16; ks++) {
        int k0 = ks * 8;
        uint32_t a0 = As[rA * PAD + k0 + kq];
        uint32_t a1 = As[(rA + 8) * PAD + k0 + kq];
        uint32_t a2 = As[rA * PAD + k0 + 4 + kq];
        uint32_t a3 = As[(rA + 8) * PAD + k0 + 4 + kq];
#pragma unroll
        for (int nt = 0; nt < 8; nt++) {
            uint32_t b0 = Bs[(nt * 8 + g) * PAD + k0 + kq];
            uint32_t b1 = Bs[(nt * 8 + g) * PAD + k0 + 4 + kq];
            asm volatile(
                "mma.sync.aligned.m16n8k8.row.col.f32.tf32.tf32.f32 "
                "{%0,%1,%2,%3}, {%4,%5,%6,%7}, {%8,%9}, {%0,%1,%2,%3};"
                : "+f"(acc[nt][0]), "+f"(acc[nt][1]), "+f"(acc[nt][2]), "+f"(acc[nt][3])
                : "r"(a0), "r"(a1), "r"(a2), "r"(a3), "r"(b0), "r"(b1));
        }
    }

    // epilogue
    int n0 = tile * 128 + warp * 16 + g;     // row for c0/c1
    int n1 = n0 + 8;                         // row for c2/c3
    if (r < 8) {
        float* base = g_hall + (size_t)r * NN * CC;
#pragma unroll
        for (int nt = 0; nt < 8; nt++) {
            int c = nt * 8 + kq * 2;
            if (n0 < NN) *(float2*)&base[(size_t)n0 * CC + c] = make_float2(acc[nt][0], acc[nt][1]);
            if (n1 < NN) *(float2*)&base[(size_t)n1 * CC + c] = make_float2(acc[nt][2], acc[nt][3]);
        }
    } else {
#pragma unroll
        for (int nt = 0; nt < 8; nt++) {
            int c = nt * 8 + kq * 2;
            float2 bb = *(const float2*)&b2[c];
            if (n0 < NN) *(float2*)&out[(size_t)n0 * CC + c] = make_float2(acc[nt][0] + bb.x, acc[nt][1] + bb.y);
            if (n1 < NN) *(float2*)&out[(size_t)n1 * CC + c] = make_float2(acc[nt][2] + bb.x, acc[nt][3] + bb.y);
        }
    }
}

// ---------------- layer 2: warp per dst, gather h_all, accumulate into out ----------------
__global__ void k_layer2(float* __restrict__ out) {
    int w = (blockIdx.x * blockDim.x + threadIdx.x) >> 5;
    int lane = threadIdx.x & 31;
    if (w >= NN) return;
    int beg = g_offs[w];
    int cnt = g_cntd[w];
    float2 acc = ((float2*)out)[w * 32 + lane];   // h@root2 + b2 from k_gemm
    const float2* hv = (const float2*)g_hall;
    int invbase = w * RRL;
    int i = 0;
    for (; i + 4 <= cnt; i += 4) {
        int p0 = g_sorted[beg + i + 0];
        int p1 = g_sorted[beg + i + 1];
        int p2 = g_sorted[beg + i + 2];
        int p3 = g_sorted[beg + i + 3];
        float s0 = g_inv[invbase + (p0 >> 16)];
        float s1 = g_inv[invbase + (p1 >> 16)];
        float s2 = g_inv[invbase + (p2 >> 16)];
        float s3 = g_inv[invbase + (p3 >> 16)];
        float2 v0 = hv[(size_t)((p0 >> 16) * NN + (p0 & 0xFFFF)) * 32 + lane];
        float2 v1 = hv[(size_t)((p1 >> 16) * NN + (p1 & 0xFFFF)) * 32 + lane];
        float2 v2 = hv[(size_t)((p2 >> 16) * NN + (p2 & 0xFFFF)) * 32 + lane];
        float2 v3 = hv[(size_t)((p3 >> 16) * NN + (p3 & 0xFFFF)) * 32 + lane];
        acc.x += v0.x*s0 + v1.x*s1 + v2.x*s2 + v3.x*s3;
        acc.y += v0.y*s0 + v1.y*s1 + v2.y*s2 + v3.y*s3;
    }
    for (; i < cnt; i++) {
        int p = g_sorted[beg + i];
        float s = g_inv[invbase + (p >> 16)];
        float2 v = hv[(size_t)((p >> 16) * NN + (p & 0xFFFF)) * 32 + lane];
        acc.x += v.x * s; acc.y += v.y * s;
    }
    ((float2*)out)[w * 32 + lane] = acc;
}

// ---------------- launch ----------------
extern "C" void kernel_launch(void* const* d_in, const int* in_sizes, int n_in,
                              void* d_out, int out_size) {
    (void)in_sizes; (void)n_in; (void)out_size;
    const int*   ei    = (const int*)d_in[0];
    const int*   et    = (const int*)d_in[1];
    const float* W1    = (const float*)d_in[2];
    const float* root1 = (const float*)d_in[3];
    const float* b1    = (const float*)d_in[4];
    const float* W2    = (const float*)d_in[5];
    const float* root2 = (const float*)d_in[6];
    const float* b2    = (const float*)d_in[7];
    float* out = (float*)d_out;

    k_fused0<<<592, 256>>>(W2, root2);
    k_hist<<<(EE + 255) / 256, 256>>>(ei, et);
    k_scan<<<40, 1024>>>();
    k_perm<<<(EE + 255) / 256, 256>>>(ei, et);
    k_layer1<<<NN / 8, 256>>>(W1, root1, b1);
    cudaFuncSetAttribute(k_gemm, cudaFuncAttributeMaxDynamicSharedMemorySize, SM_TOTAL);
    k_gemm<<<dim3(NTILES, 9), 256, SM_TOTAL>>>(b2, out);
    k_layer2<<<NN / 8, 256>>>(out);
}

// round 4
// speedup vs baseline: 2.2148x; 1.0543x over previous
#include <cuda_runtime.h>
#include <cuda_fp16.h>
#include <cstdint>

#define NN 40000
#define EE 640000
#define RRL 8
#define HH 128
#define CC 64
#define NRSEG (NN*RRL)
#define NTILES 313          // ceil(40000/128)

// ---------------- scratch (__device__ globals; no allocation) ----------------
__device__ int   g_cntd[NN];
__device__ int   g_cnt2[NRSEG];
__device__ float g_inv[NRSEG];
__device__ int   g_offs[NN];
__device__ int   g_cursor[NN];
__device__ int   g_sorted[EE];          // (rel<<16)|src, grouped by dst
__device__ float g_escale[EE];          // per-edge 1/cnt(dst,rel), CSR order
__device__ int   g_bsum[40];
__device__ int   g_bflag[40];
__device__ uint32_t g_h[(size_t)NTILES * 128 * HH];   // layer-1 out as tf32 bits
__device__ uint32_t g_w2t[9 * CC * HH];               // W2^T / root2^T tf32 bits [m][c][k]
__device__ __half g_hall[(size_t)RRL * NN * CC];      // h @ W2[r] in fp16, 41 MB (L2-resident)

__device__ __forceinline__ uint32_t f2tf(float x) {
    uint32_t r; asm("cvt.rna.tf32.f32 %0, %1;" : "=r"(r) : "f"(x)); return r;
}

// ---------------- fused: zero counters + transpose W2/root2 to tf32 [m][c][k] ----------------
__global__ void k_fused0(const float* __restrict__ W2, const float* __restrict__ root2) {
    int i = blockIdx.x * blockDim.x + threadIdx.x;
    int stride = gridDim.x * blockDim.x;
    for (int j = i; j < NRSEG; j += stride) {
        g_cnt2[j] = 0;
        if (j < NN) { g_cntd[j] = 0; g_cursor[j] = 0; }
        if (j < 40) { g_bflag[j] = 0; }
    }
    for (int j = i; j < 9 * CC * HH; j += stride) {
        int m = j >> 13;
        int rem = j & 8191;
        int c = rem >> 7;
        int k = rem & 127;
        float v = (m < 8) ? W2[((size_t)m * HH + k) * CC + c] : root2[(size_t)k * CC + c];
        g_w2t[j] = f2tf(v);
    }
}

__global__ void k_hist(const int* __restrict__ ei, const int* __restrict__ et) {
    int e = blockIdx.x * blockDim.x + threadIdx.x;
    if (e >= EE) return;
    int dst = ei[EE + e];
    int rel = et[e];
    atomicAdd(&g_cntd[dst], 1);
    atomicAdd(&g_cnt2[dst * RRL + rel], 1);
}

// ---------------- single-kernel scan (decoupled lookback) + inv ----------------
__global__ void k_scan() {
    __shared__ int s[1024];
    __shared__ int sprev;
    int b = blockIdx.x, tid = threadIdx.x;
    int i = b * 1024 + tid;
    int v = (i < NN) ? g_cntd[i] : 0;
    s[tid] = v;
    __syncthreads();
    for (int off = 1; off < 1024; off <<= 1) {
        int t = (tid >= off) ? s[tid - off] : 0;
        __syncthreads();
        s[tid] += t;
        __syncthreads();
    }
    if (tid == 1023) {
        int total = s[1023];
        int prev = 0;
        if (b > 0) {
            while (atomicAdd(&g_bflag[b - 1], 0) == 0) { }
            prev = g_bsum[b - 1];
        }
        g_bsum[b] = prev + total;
        __threadfence();
        atomicExch(&g_bflag[b], 1);
        sprev = prev;
    }
    for (int j = b * 1024 + tid; j < NRSEG; j += 40 * 1024) {
        int c = g_cnt2[j];
        g_inv[j] = 1.0f / (float)(c > 0 ? c : 1);
    }
    __syncthreads();
    if (i < NN) g_offs[i] = s[tid] - v + sprev;
}

__global__ void k_perm(const int* __restrict__ ei, const int* __restrict__ et) {
    int e = blockIdx.x * blockDim.x + threadIdx.x;
    if (e >= EE) return;
    int dst = ei[EE + e];
    int rel = et[e];
    int src = ei[e];
    int pos = g_offs[dst] + atomicAdd(&g_cursor[dst], 1);
    g_sorted[pos] = (rel << 16) | src;
    g_escale[pos] = g_inv[dst * RRL + rel];
}

// ---------------- layer 1: warp per dst, 8-deep MLP, writes tf32 bits ----------------
__global__ void k_layer1(const float* __restrict__ W1, const float* __restrict__ root1,
                         const float* __restrict__ b1) {
    int w = (blockIdx.x * blockDim.x + threadIdx.x) >> 5;
    int lane = threadIdx.x & 31;
    if (w >= NN) return;
    int beg = g_offs[w];
    int cnt = g_cntd[w];
    float4 acc = ((const float4*)root1)[w * 32 + lane];
    float4 bb = ((const float4*)b1)[lane];
    acc.x += bb.x; acc.y += bb.y; acc.z += bb.z; acc.w += bb.w;
    const float4* W1v = (const float4*)W1;
    int i = 0;
    for (; i + 8 <= cnt; i += 8) {
        int p[8]; float s[8]; float4 v[8];
#pragma unroll
        for (int j = 0; j < 8; j++) p[j] = g_sorted[beg + i + j];
#pragma unroll
        for (int j = 0; j < 8; j++) s[j] = g_escale[beg + i + j];
#pragma unroll
        for (int j = 0; j < 8; j++)
            v[j] = W1v[(size_t)((p[j] >> 16) * NN + (p[j] & 0xFFFF)) * 32 + lane];
#pragma unroll
        for (int j = 0; j < 8; j++) {
            acc.x += v[j].x * s[j];
            acc.y += v[j].y * s[j];
            acc.z += v[j].z * s[j];
            acc.w += v[j].w * s[j];
        }
    }
    for (; i < cnt; i++) {
        int p = g_sorted[beg + i];
        float s = g_escale[beg + i];
        float4 v = W1v[(size_t)((p >> 16) * NN + (p & 0xFFFF)) * 32 + lane];
        acc.x += v.x * s; acc.y += v.y * s; acc.z += v.z * s; acc.w += v.w * s;
    }
    // relu + convert to tf32 bits (A operand for the tensor GEMM)
    ((uint4*)g_h)[w * 32 + lane] = make_uint4(
        f2tf(fmaxf(acc.x, 0.0f)), f2tf(fmaxf(acc.y, 0.0f)),
        f2tf(fmaxf(acc.z, 0.0f)), f2tf(fmaxf(acc.w, 0.0f)));
}

// ---------------- GEMM via tf32 mma.sync: h_all[r] = h @ W2[r]; r==8 -> out ----------------
#define PAD 132
#define SM_TOTAL ((128 + 64) * PAD * 4)   // 101376 bytes

__global__ void __launch_bounds__(256, 2) k_gemm(const float* __restrict__ b2,
                                                 float* __restrict__ out) {
    extern __shared__ uint32_t sm32[];
    uint32_t* As = sm32;               // [128][PAD] tf32 bits
    uint32_t* Bs = sm32 + 128 * PAD;   // [64][PAD]  tf32 bits (B^T: [c][k])
    int t = threadIdx.x;
    int tile = blockIdx.x;
    int r = blockIdx.y;

    // stage A (already tf32 bits)
    const uint4* asrc = (const uint4*)(g_h + (size_t)tile * 128 * HH);
#pragma unroll
    for (int j = 0; j < 16; j++) {
        int f = t + j * 256;           // 0..4095 uint4s
        int row = f >> 5, q = f & 31;
        *(uint4*)&As[row * PAD + (q << 2)] = asrc[f];
    }
    // stage B (already tf32 bits): [c][k]
    const uint4* bsrc = (const uint4*)(g_w2t + (size_t)r * CC * HH);
#pragma unroll
    for (int j = 0; j < 8; j++) {
        int f = t + j * 256;           // 0..2047 uint4s
        int row = f >> 5, q = f & 31;
        *(uint4*)&Bs[row * PAD + (q << 2)] = bsrc[f];
    }
    __syncthreads();

    int warp = t >> 5, lane = t & 31;
    int g = lane >> 2;        // groupID 0..7
    int kq = lane & 3;        // threadID_in_group
    int rA = warp * 16 + g;

    float acc[8][4];
#pragma unroll
    for (int nt = 0; nt < 8; nt++)
#pragma unroll
        for (int q = 0; q < 4; q++) acc[nt][q] = 0.0f;

#pragma unroll
    for (int ks = 0; ks < 16; ks++) {
        int k0 = ks * 8;
        uint32_t a0 = As[rA * PAD + k0 + kq];
        uint32_t a1 = As[(rA + 8) * PAD + k0 + kq];
        uint32_t a2 = As[rA * PAD + k0 + 4 + kq];
        uint32_t a3 = As[(rA + 8) * PAD + k0 + 4 + kq];
#pragma unroll
        for (int nt = 0; nt < 8; nt++) {
            uint32_t b0 = Bs[(nt * 8 + g) * PAD + k0 + kq];
            uint32_t b1 = Bs[(nt * 8 + g) * PAD + k0 + 4 + kq];
            asm volatile(
                "mma.sync.aligned.m16n8k8.row.col.f32.tf32.tf32.f32 "
                "{%0,%1,%2,%3}, {%4,%5,%6,%7}, {%8,%9}, {%0,%1,%2,%3};"
                : "+f"(acc[nt][0]), "+f"(acc[nt][1]), "+f"(acc[nt][2]), "+f"(acc[nt][3])
                : "r"(a0), "r"(a1), "r"(a2), "r"(a3), "r"(b0), "r"(b1));
        }
    }

    // epilogue
    int n0 = tile * 128 + warp * 16 + g;     // row for c0/c1
    int n1 = n0 + 8;                         // row for c2/c3
    if (r < 8) {
        __half* base = g_hall + (size_t)r * NN * CC;
#pragma unroll
        for (int nt = 0; nt < 8; nt++) {
            int c = nt * 8 + kq * 2;
            if (n0 < NN) *(__half2*)&base[(size_t)n0 * CC + c] = __floats2half2_rn(acc[nt][0], acc[nt][1]);
            if (n1 < NN) *(__half2*)&base[(size_t)n1 * CC + c] = __floats2half2_rn(acc[nt][2], acc[nt][3]);
        }
    } else {
#pragma unroll
        for (int nt = 0; nt < 8; nt++) {
            int c = nt * 8 + kq * 2;
            float2 bb = *(const float2*)&b2[c];
            if (n0 < NN) *(float2*)&out[(size_t)n0 * CC + c] = make_float2(acc[nt][0] + bb.x, acc[nt][1] + bb.y);
            if (n1 < NN) *(float2*)&out[(size_t)n1 * CC + c] = make_float2(acc[nt][2] + bb.x, acc[nt][3] + bb.y);
        }
    }
}

// ---------------- layer 2: warp per dst, gather fp16 h_all (L2-resident) ----------------
__global__ void k_layer2(float* __restrict__ out) {
    int w = (blockIdx.x * blockDim.x + threadIdx.x) >> 5;
    int lane = threadIdx.x & 31;
    if (w >= NN) return;
    int beg = g_offs[w];
    int cnt = g_cntd[w];
    float2 acc = ((float2*)out)[w * 32 + lane];   // h@root2 + b2 from k_gemm
    const __half2* hv = (const __half2*)g_hall;
    int i = 0;
    for (; i + 8 <= cnt; i += 8) {
        int p[8]; float s[8]; __half2 v[8];
#pragma unroll
        for (int j = 0; j < 8; j++) p[j] = g_sorted[beg + i + j];
#pragma unroll
        for (int j = 0; j < 8; j++) s[j] = g_escale[beg + i + j];
#pragma unroll
        for (int j = 0; j < 8; j++)
            v[j] = hv[(size_t)((p[j] >> 16) * NN + (p[j] & 0xFFFF)) * 32 + lane];
#pragma unroll
        for (int j = 0; j < 8; j++) {
            float2 f = __half22float2(v[j]);
            acc.x += f.x * s[j];
            acc.y += f.y * s[j];
        }
    }
    for (; i < cnt; i++) {
        int p = g_sorted[beg + i];
        float s = g_escale[beg + i];
        float2 f = __half22float2(hv[(size_t)((p >> 16) * NN + (p & 0xFFFF)) * 32 + lane]);
        acc.x += f.x * s; acc.y += f.y * s;
    }
    ((float2*)out)[w * 32 + lane] = acc;
}

// ---------------- launch ----------------
extern "C" void kernel_launch(void* const* d_in, const int* in_sizes, int n_in,
                              void* d_out, int out_size) {
    (void)in_sizes; (void)n_in; (void)out_size;
    const int*   ei    = (const int*)d_in[0];
    const int*   et    = (const int*)d_in[1];
    const float* W1    = (const float*)d_in[2];
    const float* root1 = (const float*)d_in[3];
    const float* b1    = (const float*)d_in[4];
    const float* W2    = (const float*)d_in[5];
    const float* root2 = (const float*)d_in[6];
    const float* b2    = (const float*)d_in[7];
    float* out = (float*)d_out;

    k_fused0<<<592, 256>>>(W2, root2);
    k_hist<<<(EE + 255) / 256, 256>>>(ei, et);
    k_scan<<<40, 1024>>>();
    k_perm<<<(EE + 255) / 256, 256>>>(ei, et);
    k_layer1<<<NN / 8, 256>>>(W1, root1, b1);
    cudaFuncSetAttribute(k_gemm, cudaFuncAttributeMaxDynamicSharedMemorySize, SM_TOTAL);
    k_gemm<<<dim3(NTILES, 9), 256, SM_TOTAL>>>(b2, out);
    k_layer2<<<NN / 8, 256>>>(out);
}

// round 5
// speedup vs baseline: 2.2795x; 1.0292x over previous
#include <cuda_runtime.h>
#include <cuda_fp16.h>
#include <cstdint>

#define NN 40000
#define EE 640000
#define RRL 8
#define HH 128
#define CC 64
#define NRSEG (NN*RRL)
#define NTILES 313          // ceil(40000/128)

// ---------------- scratch (__device__ globals; no allocation) ----------------
__device__ int   g_cnt2[NRSEG];
__device__ float g_inv[NRSEG];
__device__ int   g_offs[NN];
__device__ int   g_cursor[NN];
__device__ int2  g_edge[EE];            // {.x=(rel<<16)|src, .y=scale bits}, dst-grouped
__device__ int   g_bsum[40];
__device__ int   g_bflag[40];
__device__ uint32_t g_h[(size_t)NTILES * 128 * HH];   // layer-1 out as tf32 bits
__device__ uint32_t g_w2t[9 * CC * HH];               // W2^T / root2^T tf32 bits [m][c][k]
__device__ __half g_hall[(size_t)RRL * NN * CC];      // h @ W2[r] in fp16, 41 MB (L2-resident)

__device__ __forceinline__ uint32_t f2tf(float x) {
    uint32_t r; asm("cvt.rna.tf32.f32 %0, %1;" : "=r"(r) : "f"(x)); return r;
}

// ---------------- fused: zero counters + transpose W2/root2 to tf32 [m][c][k] ----------------
__global__ void k_fused0(const float* __restrict__ W2, const float* __restrict__ root2) {
    int i = blockIdx.x * blockDim.x + threadIdx.x;
    int stride = gridDim.x * blockDim.x;
    for (int j = i; j < NRSEG; j += stride) {
        g_cnt2[j] = 0;
        if (j < NN) g_cursor[j] = 0;
        if (j < 40) g_bflag[j] = 0;
    }
    for (int j = i; j < 9 * CC * HH; j += stride) {
        int m = j >> 13;
        int rem = j & 8191;
        int c = rem >> 7;
        int k = rem & 127;
        float v = (m < 8) ? W2[((size_t)m * HH + k) * CC + c] : root2[(size_t)k * CC + c];
        g_w2t[j] = f2tf(v);
    }
}

__global__ void k_hist(const int* __restrict__ ei, const int* __restrict__ et) {
    int e = blockIdx.x * blockDim.x + threadIdx.x;
    if (e >= EE) return;
    int dst = ei[EE + e];
    int rel = et[e];
    atomicAdd(&g_cnt2[dst * RRL + rel], 1);
}

// ---------------- single-kernel scan (decoupled lookback) + inv ----------------
// per-dst count = sum of its 8 cnt2 entries
__global__ void k_scan() {
    __shared__ int s[1024];
    __shared__ int sprev;
    int b = blockIdx.x, tid = threadIdx.x;
    int i = b * 1024 + tid;
    int v = 0;
    if (i < NN) {
        int4 c0 = ((const int4*)g_cnt2)[i * 2];
        int4 c1 = ((const int4*)g_cnt2)[i * 2 + 1];
        v = c0.x + c0.y + c0.z + c0.w + c1.x + c1.y + c1.z + c1.w;
    }
    s[tid] = v;
    __syncthreads();
    for (int off = 1; off < 1024; off <<= 1) {
        int t = (tid >= off) ? s[tid - off] : 0;
        __syncthreads();
        s[tid] += t;
        __syncthreads();
    }
    if (tid == 1023) {
        int total = s[1023];
        int prev = 0;
        if (b > 0) {
            while (atomicAdd(&g_bflag[b - 1], 0) == 0) { }
            prev = g_bsum[b - 1];
        }
        g_bsum[b] = prev + total;
        __threadfence();
        atomicExch(&g_bflag[b], 1);
        sprev = prev;
    }
    for (int j = b * 1024 + tid; j < NRSEG; j += 40 * 1024) {
        int c = g_cnt2[j];
        g_inv[j] = 1.0f / (float)(c > 0 ? c : 1);
    }
    __syncthreads();
    if (i < NN) g_offs[i] = s[tid] - v + sprev;
}

__global__ void k_perm(const int* __restrict__ ei, const int* __restrict__ et) {
    int e = blockIdx.x * blockDim.x + threadIdx.x;
    if (e >= EE) return;
    int dst = ei[EE + e];
    int rel = et[e];
    int src = ei[e];
    int pos = g_offs[dst] + atomicAdd(&g_cursor[dst], 1);
    float s = g_inv[dst * RRL + rel];
    g_edge[pos] = make_int2((rel << 16) | src, __float_as_int(s));
}

// ---------------- layer 1: warp per dst, 8-deep MLP, writes tf32 bits ----------------
__global__ void k_layer1(const float* __restrict__ W1, const float* __restrict__ root1,
                         const float* __restrict__ b1) {
    int w = (blockIdx.x * blockDim.x + threadIdx.x) >> 5;
    int lane = threadIdx.x & 31;
    if (w >= NN) return;
    int beg = g_offs[w];
    int end = (w == NN - 1) ? EE : g_offs[w + 1];
    int cnt = end - beg;
    float4 acc = ((const float4*)root1)[w * 32 + lane];
    float4 bb = ((const float4*)b1)[lane];
    acc.x += bb.x; acc.y += bb.y; acc.z += bb.z; acc.w += bb.w;
    const float4* W1v = (const float4*)W1;
    int i = 0;
    for (; i + 8 <= cnt; i += 8) {
        int2 e[8]; float4 v[8];
#pragma unroll
        for (int j = 0; j < 8; j++) e[j] = g_edge[beg + i + j];
#pragma unroll
        for (int j = 0; j < 8; j++)
            v[j] = W1v[(size_t)((e[j].x >> 16) * NN + (e[j].x & 0xFFFF)) * 32 + lane];
#pragma unroll
        for (int j = 0; j < 8; j++) {
            float s = __int_as_float(e[j].y);
            acc.x += v[j].x * s;
            acc.y += v[j].y * s;
            acc.z += v[j].z * s;
            acc.w += v[j].w * s;
        }
    }
    for (; i < cnt; i++) {
        int2 e = g_edge[beg + i];
        float s = __int_as_float(e.y);
        float4 v = W1v[(size_t)((e.x >> 16) * NN + (e.x & 0xFFFF)) * 32 + lane];
        acc.x += v.x * s; acc.y += v.y * s; acc.z += v.z * s; acc.w += v.w * s;
    }
    ((uint4*)g_h)[w * 32 + lane] = make_uint4(
        f2tf(fmaxf(acc.x, 0.0f)), f2tf(fmaxf(acc.y, 0.0f)),
        f2tf(fmaxf(acc.z, 0.0f)), f2tf(fmaxf(acc.w, 0.0f)));
}

// ---------------- GEMM via tf32 mma.sync: A staged once, 3 r-slices per CTA ----------------
#define PAD 132
#define SM_TOTAL ((128 + 64) * PAD * 4)   // 101376 bytes

__global__ void __launch_bounds__(256, 2) k_gemm(const float* __restrict__ b2,
                                                 float* __restrict__ out) {
    extern __shared__ uint32_t sm32[];
    uint32_t* As = sm32;               // [128][PAD] tf32 bits
    uint32_t* Bs = sm32 + 128 * PAD;   // [64][PAD]  tf32 bits (B^T: [c][k])
    int t = threadIdx.x;
    int tile = blockIdx.x;
    int rbase = blockIdx.y * 3;

    // stage A once (already tf32 bits)
    const uint4* asrc = (const uint4*)(g_h + (size_t)tile * 128 * HH);
#pragma unroll
    for (int j = 0; j < 16; j++) {
        int f = t + j * 256;           // 0..4095 uint4s
        int row = f >> 5, q = f & 31;
        *(uint4*)&As[row * PAD + (q << 2)] = asrc[f];
    }

    int warp = t >> 5, lane = t & 31;
    int g = lane >> 2;        // groupID 0..7
    int kq = lane & 3;        // threadID_in_group
    int rA = warp * 16 + g;
    int n0 = tile * 128 + warp * 16 + g;
    int n1 = n0 + 8;

    for (int rr = 0; rr < 3; rr++) {
        int r = rbase + rr;
        __syncthreads();      // Bs overwrite safety + first-iter As visibility
        const uint4* bsrc = (const uint4*)(g_w2t + (size_t)r * CC * HH);
#pragma unroll
        for (int j = 0; j < 8; j++) {
            int f = t + j * 256;       // 0..2047 uint4s
            int row = f >> 5, q = f & 31;
            *(uint4*)&Bs[row * PAD + (q << 2)] = bsrc[f];
        }
        __syncthreads();

        float acc[8][4];
#pragma unroll
        for (int nt = 0; nt < 8; nt++)
#pragma unroll
            for (int q = 0; q < 4; q++) acc[nt][q] = 0.0f;

#pragma unroll
        for (int ks = 0; ks < 16; ks++) {
            int k0 = ks * 8;
            uint32_t a0 = As[rA * PAD + k0 + kq];
            uint32_t a1 = As[(rA + 8) * PAD + k0 + kq];
            uint32_t a2 = As[rA * PAD + k0 + 4 + kq];
            uint32_t a3 = As[(rA + 8) * PAD + k0 + 4 + kq];
#pragma unroll
            for (int nt = 0; nt < 8; nt++) {
                uint32_t b0 = Bs[(nt * 8 + g) * PAD + k0 + kq];
                uint32_t b1 = Bs[(nt * 8 + g) * PAD + k0 + 4 + kq];
                asm volatile(
                    "mma.sync.aligned.m16n8k8.row.col.f32.tf32.tf32.f32 "
                    "{%0,%1,%2,%3}, {%4,%5,%6,%7}, {%8,%9}, {%0,%1,%2,%3};"
                    : "+f"(acc[nt][0]), "+f"(acc[nt][1]), "+f"(acc[nt][2]), "+f"(acc[nt][3])
                    : "r"(a0), "r"(a1), "r"(a2), "r"(a3), "r"(b0), "r"(b1));
            }
        }

        if (r < 8) {
            __half* base = g_hall + (size_t)r * NN * CC;
#pragma unroll
            for (int nt = 0; nt < 8; nt++) {
                int c = nt * 8 + kq * 2;
                if (n0 < NN) *(__half2*)&base[(size_t)n0 * CC + c] = __floats2half2_rn(acc[nt][0], acc[nt][1]);
                if (n1 < NN) *(__half2*)&base[(size_t)n1 * CC + c] = __floats2half2_rn(acc[nt][2], acc[nt][3]);
            }
        } else {
#pragma unroll
            for (int nt = 0; nt < 8; nt++) {
                int c = nt * 8 + kq * 2;
                float2 bb = *(const float2*)&b2[c];
                if (n0 < NN) *(float2*)&out[(size_t)n0 * CC + c] = make_float2(acc[nt][0] + bb.x, acc[nt][1] + bb.y);
                if (n1 < NN) *(float2*)&out[(size_t)n1 * CC + c] = make_float2(acc[nt][2] + bb.x, acc[nt][3] + bb.y);
            }
        }
    }
}

// ---------------- layer 2: warp per dst, gather fp16 h_all (L2-resident) ----------------
__global__ void k_layer2(float* __restrict__ out) {
    int w = (blockIdx.x * blockDim.x + threadIdx.x) >> 5;
    int lane = threadIdx.x & 31;
    if (w >= NN) return;
    int beg = g_offs[w];
    int end = (w == NN - 1) ? EE : g_offs[w + 1];
    int cnt = end - beg;
    float2 acc = ((float2*)out)[w * 32 + lane];   // h@root2 + b2 from k_gemm
    const __half2* hv = (const __half2*)g_hall;
    int i = 0;
    for (; i + 8 <= cnt; i += 8) {
        int2 e[8]; __half2 v[8];
#pragma unroll
        for (int j = 0; j < 8; j++) e[j] = g_edge[beg + i + j];
#pragma unroll
        for (int j = 0; j < 8; j++)
            v[j] = hv[(size_t)((e[j].x >> 16) * NN + (e[j].x & 0xFFFF)) * 32 + lane];
#pragma unroll
        for (int j = 0; j < 8; j++) {
            float s = __int_as_float(e[j].y);
            float2 f = __half22float2(v[j]);
            acc.x += f.x * s;
            acc.y += f.y * s;
        }
    }
    for (; i < cnt; i++) {
        int2 e = g_edge[beg + i];
        float s = __int_as_float(e.y);
        float2 f = __half22float2(hv[(size_t)((e.x >> 16) * NN + (e.x & 0xFFFF)) * 32 + lane]);
        acc.x += f.x * s; acc.y += f.y * s;
    }
    ((float2*)out)[w * 32 + lane] = acc;
}

// ---------------- launch ----------------
extern "C" void kernel_launch(void* const* d_in, const int* in_sizes, int n_in,
                              void* d_out, int out_size) {
    (void)in_sizes; (void)n_in; (void)out_size;
    const int*   ei    = (const int*)d_in[0];
    const int*   et    = (const int*)d_in[1];
    const float* W1    = (const float*)d_in[2];
    const float* root1 = (const float*)d_in[3];
    const float* b1    = (const float*)d_in[4];
    const float* W2    = (const float*)d_in[5];
    const float* root2 = (const float*)d_in[6];
    const float* b2    = (const float*)d_in[7];
    float* out = (float*)d_out;

    k_fused0<<<592, 256>>>(W2, root2);
    k_hist<<<(EE + 255) / 256, 256>>>(ei, et);
    k_scan<<<40, 1024>>>();
    k_perm<<<(EE + 255) / 256, 256>>>(ei, et);
    k_layer1<<<NN / 8, 256>>>(W1, root1, b1);
    cudaFuncSetAttribute(k_gemm, cudaFuncAttributeMaxDynamicSharedMemorySize, SM_TOTAL);
    k_gemm<<<dim3(NTILES, 3), 256, SM_TOTAL>>>(b2, out);
    k_layer2<<<NN / 8, 256>>>(out);
}